// round 13
// baseline (speedup 1.0000x reference)
#include <cuda_runtime.h>
#include <cuda_fp16.h>
#include <cstdint>

#define N_EXPERTS 8
#define FDIM1 1024
#define FDIM2 512
#define NCLS 64
#define BATCH 16384
#define APITCH1 72   // smem pitch for K-chunk 64 (64 + 8 pad), conflict-free ldmatrix

// ---------------- scratch (static device arrays; allocation-free) ----------
__device__ __align__(16) __half g_W1t[N_EXPERTS * FDIM2 * FDIM1];
__device__ __align__(16) __half g_W2t[N_EXPERTS * NCLS * FDIM2];
__device__ __align__(16) __half g_X16[(size_t)BATCH * FDIM1];
__device__ __align__(16) __half g_H[(size_t)BATCH * FDIM2];
__device__ int g_idx[N_EXPERTS * BATCH];
__device__ int g_cnt[N_EXPERTS];   // reset each launch in k_convX

// ---------------- helpers ---------------------------------------------------
__device__ __forceinline__ uint32_t smem_u32(const void* p) {
    uint32_t a;
    asm("{ .reg .u64 t; cvta.to.shared.u64 t, %1; cvt.u32.u64 %0, t; }"
        : "=r"(a) : "l"(p));
    return a;
}

__device__ __forceinline__ void ldsm4(uint32_t& r0, uint32_t& r1, uint32_t& r2,
                                      uint32_t& r3, uint32_t addr) {
    asm volatile("ldmatrix.sync.aligned.m8n8.x4.shared.b16 {%0,%1,%2,%3}, [%4];"
                 : "=r"(r0), "=r"(r1), "=r"(r2), "=r"(r3) : "r"(addr));
}

__device__ __forceinline__ void mma_fp16(float* c, const uint32_t* a,
                                         uint32_t b0, uint32_t b1) {
    asm volatile(
        "mma.sync.aligned.m16n8k16.row.col.f32.f16.f16.f32 "
        "{%0,%1,%2,%3}, {%4,%5,%6,%7}, {%8,%9}, {%0,%1,%2,%3};"
        : "+f"(c[0]), "+f"(c[1]), "+f"(c[2]), "+f"(c[3])
        : "r"(a[0]), "r"(a[1]), "r"(a[2]), "r"(a[3]), "r"(b0), "r"(b1));
}

__device__ __forceinline__ void cpasync16(uint32_t dst, const void* src) {
    asm volatile("cp.async.ca.shared.global [%0], [%1], 16;"
                 :: "r"(dst), "l"(src) : "memory");
}
__device__ __forceinline__ void cpasync16z(uint32_t dst, const void* src, int sz) {
    asm volatile("cp.async.ca.shared.global [%0], [%1], 16, %2;"
                 :: "r"(dst), "l"(src), "r"(sz) : "memory");
}
#define CP_COMMIT() asm volatile("cp.async.commit_group;" ::: "memory")
#define CP_WAIT(n) asm volatile("cp.async.wait_group %0;" ::"n"(n) : "memory")

__device__ __forceinline__ uint32_t packh2(float v0, float v1) {
    __half2 h = __floats2half2_rn(v0, v1);
    return *(uint32_t*)&h;
}

// ---------------- prep kernels ----------------------------------------------
// convX also resets g_cnt (completes before k_convW's bucket blocks run)
__global__ void k_convX(const float* __restrict__ src) {
    if (blockIdx.x == 0 && threadIdx.x < N_EXPERTS) g_cnt[threadIdx.x] = 0;
    size_t i = ((size_t)blockIdx.x * blockDim.x + threadIdx.x) * 8;
    float4 a = *(const float4*)(src + i);
    float4 b = *(const float4*)(src + i + 4);
    uint4 o = make_uint4(packh2(a.x, a.y), packh2(a.z, a.w),
                         packh2(b.x, b.y), packh2(b.z, b.w));
    *(uint4*)(&g_X16[i]) = o;
}

// Merged: W1 transpose-convert, W2 transpose-convert, AND expert bucketing
// (bucket runs in the otherwise-idle blocks y>=16 && x>=16).
__global__ void k_convW(const float* __restrict__ W1,
                        const float* __restrict__ W2,
                        const int* __restrict__ domain) {
    __shared__ float tile[32][33];
    int e = blockIdx.z;
    int tx = threadIdx.x, ty = threadIdx.y;
    if (blockIdx.y < 16) {
        int kb = blockIdx.x * 32, nb = blockIdx.y * 32;
        const float* s = W1 + ((size_t)e * FDIM1 + kb) * FDIM2 + nb;
#pragma unroll
        for (int i = 0; i < 32; i += 8) tile[ty + i][tx] = s[(size_t)(ty + i) * FDIM2 + tx];
        __syncthreads();
        size_t ob = ((size_t)e * FDIM2 + nb) * FDIM1 + kb;
#pragma unroll
        for (int i = 0; i < 32; i += 8)
            g_W1t[ob + (size_t)(ty + i) * FDIM1 + tx] = __float2half_rn(tile[tx][ty + i]);
    } else if (blockIdx.x < 16) {
        int kb = blockIdx.x * 32, nb = (blockIdx.y - 16) * 32;
        const float* s = W2 + ((size_t)e * FDIM2 + kb) * NCLS + nb;
#pragma unroll
        for (int i = 0; i < 32; i += 8) tile[ty + i][tx] = s[(size_t)(ty + i) * NCLS + tx];
        __syncthreads();
        size_t ob = ((size_t)e * NCLS + nb) * FDIM2 + kb;
#pragma unroll
        for (int i = 0; i < 32; i += 8)
            g_W2t[ob + (size_t)(ty + i) * FDIM2 + tx] = __float2half_rn(tile[tx][ty + i]);
    } else {
        // bucket: 256 spare blocks x 256 threads; need first 64 blocks
        int bi = (e * 2 + (blockIdx.y - 16)) * 16 + (blockIdx.x - 16);  // 0..255
        if (bi < 64) {
            int i = bi * 256 + ty * 32 + tx;
            int ex = domain[i];
            int p = atomicAdd(&g_cnt[ex], 1);
            g_idx[ex * BATCH + p] = i;
        }
    }
}

// ---------------- layer 1: fp16 mma.sync GEMM, warp tile 64x64, occ 3 -------
// CTA: 128 rows x 128 cols, K=1024 in 16 chunks of 64.
// 128 threads = 4 warps = 2(M) x 2(N), each warp computes 64x64.
// 2-stage double buffer; A (ZFILL gather) + B via cp.async + wait(1).
#define L1_ROWS 0
#define L1_BIAS 512
#define L1_BASE 1024
#define L1_ASTG 18432
#define L1_STG 36864
#define L1_SMEM (1024 + 2 * L1_STG)

__global__ __launch_bounds__(128, 3) void k_gemm1(const float* __restrict__ b1)
{
    const int e = blockIdx.z;
    const int cnt = g_cnt[e];
    const int mbase = blockIdx.x * 128;
    if (mbase >= cnt) return;
    const int nbase = blockIdx.y * 128;

    extern __shared__ __align__(16) char sm1[];
    int* rows = (int*)(sm1 + L1_ROWS);
    float* bias = (float*)(sm1 + L1_BIAS);
    const uint32_t sb = smem_u32(sm1);

    const int t = threadIdx.x;
    {
        int p = mbase + t;
        rows[t] = (p < cnt) ? g_idx[e * BATCH + p] : -1;
        bias[t] = b1[e * FDIM2 + nbase + t];
    }
    __syncthreads();

    // loader mappings: thread t -> rows lr0=t>>1, lr1=lr0+64; segment seg=t&1
    const int lr0 = t >> 1;
    const int lr1 = lr0 + 64;
    const int seg = t & 1;
    const int xr0 = rows[lr0], xr1 = rows[lr1];
    const __half* xp0 = (xr0 >= 0) ? g_X16 + (size_t)xr0 * FDIM1 + seg * 32 : g_X16;
    const __half* xp1 = (xr1 >= 0) ? g_X16 + (size_t)xr1 * FDIM1 + seg * 32 : g_X16;
    const int xsz0 = (xr0 >= 0) ? 16 : 0;
    const int xsz1 = (xr1 >= 0) ? 16 : 0;
    const __half* wp0 = g_W1t + (size_t)(e * FDIM2 + nbase + lr0) * FDIM1 + seg * 32;
    const uint32_t tOff0 = lr0 * (APITCH1 * 2) + seg * 64;
    const uint32_t tOff1 = lr1 * (APITCH1 * 2) + seg * 64;
    const size_t wstride = (size_t)64 * FDIM1;  // wp1 = wp0 + wstride

#define L1_ISSUE(kc, stg)                                                  \
    do {                                                                   \
        uint32_t ba = sb + L1_BASE + (stg) * L1_STG;                       \
        cpasync16z(ba + tOff0,      xp0 + (kc), xsz0);                     \
        cpasync16z(ba + tOff0 + 16, xp0 + (kc) + 8, xsz0);                 \
        cpasync16z(ba + tOff0 + 32, xp0 + (kc) + 16, xsz0);                \
        cpasync16z(ba + tOff0 + 48, xp0 + (kc) + 24, xsz0);                \
        cpasync16z(ba + tOff1,      xp1 + (kc), xsz1);                     \
        cpasync16z(ba + tOff1 + 16, xp1 + (kc) + 8, xsz1);                 \
        cpasync16z(ba + tOff1 + 32, xp1 + (kc) + 16, xsz1);                \
        cpasync16z(ba + tOff1 + 48, xp1 + (kc) + 24, xsz1);                \
        uint32_t bb = ba + L1_ASTG;                                        \
        cpasync16(bb + tOff0,      wp0 + (kc));                            \
        cpasync16(bb + tOff0 + 16, wp0 + (kc) + 8);                        \
        cpasync16(bb + tOff0 + 32, wp0 + (kc) + 16);                       \
        cpasync16(bb + tOff0 + 48, wp0 + (kc) + 24);                       \
        cpasync16(bb + tOff1,      wp0 + wstride + (kc));                  \
        cpasync16(bb + tOff1 + 16, wp0 + wstride + (kc) + 8);              \
        cpasync16(bb + tOff1 + 32, wp0 + wstride + (kc) + 16);             \
        cpasync16(bb + tOff1 + 48, wp0 + wstride + (kc) + 24);             \
        CP_COMMIT();                                                       \
    } while (0)

    const int l = t & 31, wid = t >> 5;          // 4 warps
    const int wm = (wid >> 1) * 64, wn = (wid & 1) * 64;
    const int lrow = l & 15;
    const int lk = (l >> 4) * 8;

    float acc[4][8][4];
#pragma unroll
    for (int i = 0; i < 4; i++)
#pragma unroll
        for (int j = 0; j < 8; j++)
#pragma unroll
            for (int q = 0; q < 4; q++) acc[i][j][q] = 0.f;

    L1_ISSUE(0, 0);

    for (int c = 0; c < 16; c++) {
        const int stg = c & 1;
        if (c + 1 < 16) {
            L1_ISSUE((c + 1) * 64, stg ^ 1);  // next chunk into other stage
            CP_WAIT(1);                       // chunk c landed
        } else {
            CP_WAIT(0);
        }
        __syncthreads();

        const uint32_t aA = sb + L1_BASE + stg * L1_STG;
        const uint32_t aB = aA + L1_ASTG;
#pragma unroll
        for (int ks = 0; ks < 64; ks += 16) {
            uint32_t ah[4][4];
#pragma unroll
            for (int mt = 0; mt < 4; mt++) {
                uint32_t off = ((wm + mt * 16 + lrow) * APITCH1 + ks + lk) * 2;
                ldsm4(ah[mt][0], ah[mt][1], ah[mt][2], ah[mt][3], aA + off);
            }
            // per B-ldmatrix: load 4 regs, immediately consume with 8 MMAs
#pragma unroll
            for (int bg = 0; bg < 4; bg++) {
                uint32_t off = ((wn + bg * 16 + lrow) * APITCH1 + ks + lk) * 2;
                uint32_t r0, r1, r2, r3;
                ldsm4(r0, r1, r2, r3, aB + off);
#pragma unroll
                for (int mt = 0; mt < 4; mt++) {
                    mma_fp16(acc[mt][2 * bg],     ah[mt], r0, r2);
                    mma_fp16(acc[mt][2 * bg + 1], ah[mt], r1, r3);
                }
            }
        }
        __syncthreads();  // compute(c) done: stage stg reusable at c+1's issue
    }

    // epilogue: + bias, relu, fp16, scatter to g_H
#pragma unroll
    for (int mt = 0; mt < 4; mt++) {
        int r0i = wm + mt * 16 + (l >> 2);
        int ra = rows[r0i], rb = rows[r0i + 8];
#pragma unroll
        for (int nt = 0; nt < 8; nt++) {
            int cl = wn + nt * 8 + (l & 3) * 2;
            float b0 = bias[cl], b1v = bias[cl + 1];
            if (ra >= 0) {
                uint32_t h = packh2(fmaxf(acc[mt][nt][0] + b0, 0.f),
                                    fmaxf(acc[mt][nt][1] + b1v, 0.f));
                *(uint32_t*)(&g_H[(size_t)ra * FDIM2 + nbase + cl]) = h;
            }
            if (rb >= 0) {
                uint32_t h = packh2(fmaxf(acc[mt][nt][2] + b0, 0.f),
                                    fmaxf(acc[mt][nt][3] + b1v, 0.f));
                *(uint32_t*)(&g_H[(size_t)rb * FDIM2 + nbase + cl]) = h;
            }
        }
    }
#undef L1_ISSUE
}

// ---------------- layer 2: fp16 mma.sync, K-chunk 64, cp.async, softmax -----
// CTA: 128 rows x 64 cols, K=512 in 8 chunks of 64. 8 warps = 4(M) x 2(N).
#define L2_ROWS 0
#define L2_B2S 512
#define L2_BASE 1024
#define L2_ASTG 18432
#define L2_STG 27648
#define L2_SMEM (1024 + 2 * L2_STG)

__global__ __launch_bounds__(256) void k_gemm2(
    const float* __restrict__ b2, float* __restrict__ out)
{
    const int e = blockIdx.y;
    const int cnt = g_cnt[e];
    const int mbase = blockIdx.x * 128;
    if (mbase >= cnt) return;

    extern __shared__ __align__(16) char sm2[];
    int* rows = (int*)(sm2 + L2_ROWS);
    float* b2s = (float*)(sm2 + L2_B2S);
    const uint32_t sb = smem_u32(sm2);

    const int t = threadIdx.x;
    if (t < 128) {
        int p = mbase + t;
        rows[t] = (p < cnt) ? g_idx[e * BATCH + p] : -1;
    }
    if (t < 64) b2s[t] = b2[e * NCLS + t];
    __syncthreads();

    const int lr = t >> 1;
    const int seg = t & 1;
    const int hr = rows[lr];
    const __half* hp = (hr >= 0) ? g_H + (size_t)hr * FDIM2 + seg * 32 : g_H;
    const int hsz = (hr >= 0) ? 16 : 0;
    const uint32_t aOff = lr * (APITCH1 * 2) + seg * 64;
    const int br = t >> 2, bs = t & 3;
    const __half* wp = g_W2t + (size_t)(e * NCLS + br) * FDIM2 + bs * 16;
    const uint32_t bOff = br * (APITCH1 * 2) + bs * 32;

#define L2_ISSUE(kc, stg)                                                  \
    do {                                                                   \
        uint32_t ba = sb + L2_BASE + (stg) * L2_STG;                       \
        cpasync16z(ba + aOff,      hp + (kc), hsz);                        \
        cpasync16z(ba + aOff + 16, hp + (kc) + 8, hsz);                    \
        cpasync16z(ba + aOff + 32, hp + (kc) + 16, hsz);                   \
        cpasync16z(ba + aOff + 48, hp + (kc) + 24, hsz);                   \
        cpasync16(ba + L2_ASTG + bOff,      wp + (kc));                    \
        cpasync16(ba + L2_ASTG + bOff + 16, wp + (kc) + 8);                \
        CP_COMMIT();                                                       \
    } while (0)

    const int l = t & 31, wid = t >> 5;
    const int wm = (wid >> 1) * 32, wn = (wid & 1) * 32;
    const int lrow = l & 15;
    const int lk = (l >> 4) * 8;

    float acc[2][4][4];
#pragma unroll
    for (int i = 0; i < 2; i++)
#pragma unroll
        for (int j = 0; j < 4; j++)
#pragma unroll
            for (int q = 0; q < 4; q++) acc[i][j][q] = 0.f;

    L2_ISSUE(0, 0);

    for (int c = 0; c < 8; c++) {
        const int stg = c & 1;
        __syncthreads();
        if (c + 1 < 8) {
            L2_ISSUE((c + 1) * 64, stg ^ 1);
            CP_WAIT(1);
        } else {
            CP_WAIT(0);
        }
        __syncthreads();

        const uint32_t aA = sb + L2_BASE + stg * L2_STG;
        const uint32_t aB = aA + L2_ASTG;
#pragma unroll
        for (int ks = 0; ks < 64; ks += 16) {
            uint32_t ah[2][4];
#pragma unroll
            for (int mt = 0; mt < 2; mt++) {
                uint32_t off = ((wm + mt * 16 + lrow) * APITCH1 + ks + lk) * 2;
                ldsm4(ah[mt][0], ah[mt][1], ah[mt][2], ah[mt][3], aA + off);
            }
#pragma unroll
            for (int bg = 0; bg < 2; bg++) {
                uint32_t off = ((wn + bg * 16 + lrow) * APITCH1 + ks + lk) * 2;
                uint32_t r0, r1, r2, r3;
                ldsm4(r0, r1, r2, r3, aB + off);
#pragma unroll
                for (int mt = 0; mt < 2; mt++) {
                    mma_fp16(acc[mt][2 * bg],     ah[mt], r0, r2);
                    mma_fp16(acc[mt][2 * bg + 1], ah[mt], r1, r3);
                }
            }
        }
    }

    // logits -> smem (stage union), then per-thread softmax
    __syncthreads();
    float* lg = (float*)(sm2 + L2_BASE);  // [128][68]
#pragma unroll
    for (int mt = 0; mt < 2; mt++) {
        int r0i = wm + mt * 16 + (l >> 2);
#pragma unroll
        for (int nt = 0; nt < 4; nt++) {
            int cl = wn + nt * 8 + (l & 3) * 2;
            lg[r0i * 68 + cl]           = acc[mt][nt][0];
            lg[r0i * 68 + cl + 1]       = acc[mt][nt][1];
            lg[(r0i + 8) * 68 + cl]     = acc[mt][nt][2];
            lg[(r0i + 8) * 68 + cl + 1] = acc[mt][nt][3];
        }
    }
    __syncthreads();

    if (t < 128) {
        int r = rows[t];
        if (r >= 0) {
            float v[64];
            float mx = -3.4e38f;
#pragma unroll
            for (int j = 0; j < 64; j++) {
                v[j] = lg[t * 68 + j] + b2s[j];
                mx = fmaxf(mx, v[j]);
            }
            float s = 0.f;
#pragma unroll
            for (int j = 0; j < 64; j++) {
                v[j] = __expf(v[j] - mx);
                s += v[j];
            }
            float inv = 1.0f / s;
            float4* op = (float4*)(out + (size_t)r * NCLS);
#pragma unroll
            for (int q = 0; q < 16; q++)
                op[q] = make_float4(v[4 * q] * inv, v[4 * q + 1] * inv,
                                    v[4 * q + 2] * inv, v[4 * q + 3] * inv);
        }
    }
#undef L2_ISSUE
}

// ---------------------------------------------------------------------------
extern "C" void kernel_launch(void* const* d_in, const int* in_sizes, int n_in,
                              void* d_out, int out_size)
{
    const int*   domain = (const int*)  d_in[0];
    const float* x      = (const float*)d_in[1];
    const float* W1     = (const float*)d_in[2];
    const float* b1     = (const float*)d_in[3];
    const float* W2     = (const float*)d_in[4];
    const float* b2     = (const float*)d_in[5];
    float* out = (float*)d_out;

    cudaFuncSetAttribute(k_gemm1, cudaFuncAttributeMaxDynamicSharedMemorySize, L1_SMEM);
    cudaFuncSetAttribute(k_gemm2, cudaFuncAttributeMaxDynamicSharedMemorySize, L2_SMEM);

    k_convX<<<(BATCH * FDIM1 / 8) / 256, 256>>>(x);                    // + counter reset
    k_convW<<<dim3(32, 18, N_EXPERTS), dim3(32, 8)>>>(W1, W2, domain); // + bucket
    k_gemm1<<<dim3(BATCH / 128, FDIM2 / 128, N_EXPERTS), 128, L1_SMEM>>>(b1);
    k_gemm2<<<dim3(BATCH / 128, N_EXPERTS), 256, L2_SMEM>>>(b2, out);
}

// round 14
// speedup vs baseline: 1.2737x; 1.2737x over previous
#include <cuda_runtime.h>
#include <cuda_fp16.h>
#include <cstdint>

#define N_EXPERTS 8
#define FDIM1 1024
#define FDIM2 512
#define NCLS 64
#define BATCH 16384
#define APITCH1 72   // smem pitch for K-chunk 64 (64 + 8 pad), conflict-free ldmatrix

// ---------------- scratch (static device arrays; allocation-free) ----------
__device__ __align__(16) __half g_W1t[N_EXPERTS * FDIM2 * FDIM1];
__device__ __align__(16) __half g_W2t[N_EXPERTS * NCLS * FDIM2];
__device__ __align__(16) __half g_X16[(size_t)BATCH * FDIM1];
__device__ __align__(16) __half g_H[(size_t)BATCH * FDIM2];
__device__ int g_idx[N_EXPERTS * BATCH];
__device__ int g_cnt[N_EXPERTS];   // reset each launch in k_convX

// ---------------- helpers ---------------------------------------------------
__device__ __forceinline__ uint32_t smem_u32(const void* p) {
    uint32_t a;
    asm("{ .reg .u64 t; cvta.to.shared.u64 t, %1; cvt.u32.u64 %0, t; }"
        : "=r"(a) : "l"(p));
    return a;
}

__device__ __forceinline__ void ldsm4(uint32_t& r0, uint32_t& r1, uint32_t& r2,
                                      uint32_t& r3, uint32_t addr) {
    asm volatile("ldmatrix.sync.aligned.m8n8.x4.shared.b16 {%0,%1,%2,%3}, [%4];"
                 : "=r"(r0), "=r"(r1), "=r"(r2), "=r"(r3) : "r"(addr));
}

__device__ __forceinline__ void mma_fp16(float* c, const uint32_t* a,
                                         uint32_t b0, uint32_t b1) {
    asm volatile(
        "mma.sync.aligned.m16n8k16.row.col.f32.f16.f16.f32 "
        "{%0,%1,%2,%3}, {%4,%5,%6,%7}, {%8,%9}, {%0,%1,%2,%3};"
        : "+f"(c[0]), "+f"(c[1]), "+f"(c[2]), "+f"(c[3])
        : "r"(a[0]), "r"(a[1]), "r"(a[2]), "r"(a[3]), "r"(b0), "r"(b1));
}

__device__ __forceinline__ void cpasync16(uint32_t dst, const void* src) {
    asm volatile("cp.async.ca.shared.global [%0], [%1], 16;"
                 :: "r"(dst), "l"(src) : "memory");
}
__device__ __forceinline__ void cpasync16z(uint32_t dst, const void* src, int sz) {
    asm volatile("cp.async.ca.shared.global [%0], [%1], 16, %2;"
                 :: "r"(dst), "l"(src), "r"(sz) : "memory");
}
#define CP_COMMIT() asm volatile("cp.async.commit_group;" ::: "memory")
#define CP_WAIT(n) asm volatile("cp.async.wait_group %0;" ::"n"(n) : "memory")

__device__ __forceinline__ uint32_t packh2(float v0, float v1) {
    __half2 h = __floats2half2_rn(v0, v1);
    return *(uint32_t*)&h;
}

// ---------------- prep kernels ----------------------------------------------
// convX also resets g_cnt (completes before k_convW's bucket blocks run)
__global__ void k_convX(const float* __restrict__ src) {
    if (blockIdx.x == 0 && threadIdx.x < N_EXPERTS) g_cnt[threadIdx.x] = 0;
    size_t i = ((size_t)blockIdx.x * blockDim.x + threadIdx.x) * 8;
    float4 a = *(const float4*)(src + i);
    float4 b = *(const float4*)(src + i + 4);
    uint4 o = make_uint4(packh2(a.x, a.y), packh2(a.z, a.w),
                         packh2(b.x, b.y), packh2(b.z, b.w));
    *(uint4*)(&g_X16[i]) = o;
}

// Merged: W1 transpose-convert, W2 transpose-convert, AND expert bucketing
// (bucket runs in the otherwise-idle blocks y>=16 && x>=16).
__global__ void k_convW(const float* __restrict__ W1,
                        const float* __restrict__ W2,
                        const int* __restrict__ domain) {
    __shared__ float tile[32][33];
    int e = blockIdx.z;
    int tx = threadIdx.x, ty = threadIdx.y;
    if (blockIdx.y < 16) {
        int kb = blockIdx.x * 32, nb = blockIdx.y * 32;
        const float* s = W1 + ((size_t)e * FDIM1 + kb) * FDIM2 + nb;
#pragma unroll
        for (int i = 0; i < 32; i += 8) tile[ty + i][tx] = s[(size_t)(ty + i) * FDIM2 + tx];
        __syncthreads();
        size_t ob = ((size_t)e * FDIM2 + nb) * FDIM1 + kb;
#pragma unroll
        for (int i = 0; i < 32; i += 8)
            g_W1t[ob + (size_t)(ty + i) * FDIM1 + tx] = __float2half_rn(tile[tx][ty + i]);
    } else if (blockIdx.x < 16) {
        int kb = blockIdx.x * 32, nb = (blockIdx.y - 16) * 32;
        const float* s = W2 + ((size_t)e * FDIM2 + kb) * NCLS + nb;
#pragma unroll
        for (int i = 0; i < 32; i += 8) tile[ty + i][tx] = s[(size_t)(ty + i) * NCLS + tx];
        __syncthreads();
        size_t ob = ((size_t)e * NCLS + nb) * FDIM2 + kb;
#pragma unroll
        for (int i = 0; i < 32; i += 8)
            g_W2t[ob + (size_t)(ty + i) * FDIM2 + tx] = __float2half_rn(tile[tx][ty + i]);
    } else {
        // bucket: 256 spare blocks x 256 threads; need first 64 blocks
        int bi = (e * 2 + (blockIdx.y - 16)) * 16 + (blockIdx.x - 16);  // 0..255
        if (bi < 64) {
            int i = bi * 256 + ty * 32 + tx;
            int ex = domain[i];
            int p = atomicAdd(&g_cnt[ex], 1);
            g_idx[ex * BATCH + p] = i;
        }
    }
}

// ---------------- layer 1: fp16 mma.sync GEMM, warp tile 64x64 --------------
// CTA: 128 rows x 128 cols, K=1024 in 16 chunks of 64.
// 128 threads = 4 warps = 2(M) x 2(N), each warp computes 64x64.
// 2-stage double buffer; A (ZFILL gather) + B via cp.async + wait(1).
// (R12 version: occ 2, regs unconstrained beyond 128,2)
#define L1_ROWS 0
#define L1_BIAS 512
#define L1_BASE 1024
#define L1_ASTG 18432
#define L1_STG 36864
#define L1_SMEM (1024 + 2 * L1_STG)

__global__ __launch_bounds__(128, 2) void k_gemm1(const float* __restrict__ b1)
{
    const int e = blockIdx.z;
    const int cnt = g_cnt[e];
    const int mbase = blockIdx.x * 128;
    if (mbase >= cnt) return;
    const int nbase = blockIdx.y * 128;

    extern __shared__ __align__(16) char sm1[];
    int* rows = (int*)(sm1 + L1_ROWS);
    float* bias = (float*)(sm1 + L1_BIAS);
    const uint32_t sb = smem_u32(sm1);

    const int t = threadIdx.x;
    {
        int p = mbase + t;
        rows[t] = (p < cnt) ? g_idx[e * BATCH + p] : -1;
        bias[t] = b1[e * FDIM2 + nbase + t];
    }
    __syncthreads();

    // loader mappings: thread t -> rows lr0=t>>1, lr1=lr0+64; segment seg=t&1
    const int lr0 = t >> 1;
    const int lr1 = lr0 + 64;
    const int seg = t & 1;
    const int xr0 = rows[lr0], xr1 = rows[lr1];
    const __half* xp0 = (xr0 >= 0) ? g_X16 + (size_t)xr0 * FDIM1 + seg * 32 : g_X16;
    const __half* xp1 = (xr1 >= 0) ? g_X16 + (size_t)xr1 * FDIM1 + seg * 32 : g_X16;
    const int xsz0 = (xr0 >= 0) ? 16 : 0;
    const int xsz1 = (xr1 >= 0) ? 16 : 0;
    const __half* wp0 = g_W1t + (size_t)(e * FDIM2 + nbase + lr0) * FDIM1 + seg * 32;
    const __half* wp1 = g_W1t + (size_t)(e * FDIM2 + nbase + lr1) * FDIM1 + seg * 32;
    const uint32_t tOff0 = lr0 * (APITCH1 * 2) + seg * 64;
    const uint32_t tOff1 = lr1 * (APITCH1 * 2) + seg * 64;

#define L1_ISSUE(kc, stg)                                                  \
    do {                                                                   \
        uint32_t ba = sb + L1_BASE + (stg) * L1_STG;                       \
        cpasync16z(ba + tOff0,      xp0 + (kc), xsz0);                     \
        cpasync16z(ba + tOff0 + 16, xp0 + (kc) + 8, xsz0);                 \
        cpasync16z(ba + tOff0 + 32, xp0 + (kc) + 16, xsz0);                \
        cpasync16z(ba + tOff0 + 48, xp0 + (kc) + 24, xsz0);                \
        cpasync16z(ba + tOff1,      xp1 + (kc), xsz1);                     \
        cpasync16z(ba + tOff1 + 16, xp1 + (kc) + 8, xsz1);                 \
        cpasync16z(ba + tOff1 + 32, xp1 + (kc) + 16, xsz1);                \
        cpasync16z(ba + tOff1 + 48, xp1 + (kc) + 24, xsz1);                \
        uint32_t bb = ba + L1_ASTG;                                        \
        cpasync16(bb + tOff0,      wp0 + (kc));                            \
        cpasync16(bb + tOff0 + 16, wp0 + (kc) + 8);                        \
        cpasync16(bb + tOff0 + 32, wp0 + (kc) + 16);                       \
        cpasync16(bb + tOff0 + 48, wp0 + (kc) + 24);                       \
        cpasync16(bb + tOff1,      wp1 + (kc));                            \
        cpasync16(bb + tOff1 + 16, wp1 + (kc) + 8);                        \
        cpasync16(bb + tOff1 + 32, wp1 + (kc) + 16);                       \
        cpasync16(bb + tOff1 + 48, wp1 + (kc) + 24);                       \
        CP_COMMIT();                                                       \
    } while (0)

    const int l = t & 31, wid = t >> 5;          // 4 warps
    const int wm = (wid >> 1) * 64, wn = (wid & 1) * 64;
    const int lrow = l & 15;
    const int lk = (l >> 4) * 8;

    float acc[4][8][4];
#pragma unroll
    for (int i = 0; i < 4; i++)
#pragma unroll
        for (int j = 0; j < 8; j++)
#pragma unroll
            for (int q = 0; q < 4; q++) acc[i][j][q] = 0.f;

    L1_ISSUE(0, 0);

    for (int c = 0; c < 16; c++) {
        const int stg = c & 1;
        if (c + 1 < 16) {
            L1_ISSUE((c + 1) * 64, stg ^ 1);  // next chunk into other stage
            CP_WAIT(1);                       // chunk c landed
        } else {
            CP_WAIT(0);
        }
        __syncthreads();

        const uint32_t aA = sb + L1_BASE + stg * L1_STG;
        const uint32_t aB = aA + L1_ASTG;
#pragma unroll
        for (int ks = 0; ks < 64; ks += 16) {
            uint32_t ah[4][4], bh[8][2];
#pragma unroll
            for (int mt = 0; mt < 4; mt++) {
                uint32_t off = ((wm + mt * 16 + lrow) * APITCH1 + ks + lk) * 2;
                ldsm4(ah[mt][0], ah[mt][1], ah[mt][2], ah[mt][3], aA + off);
            }
#pragma unroll
            for (int bg = 0; bg < 4; bg++) {
                uint32_t off = ((wn + bg * 16 + lrow) * APITCH1 + ks + lk) * 2;
                uint32_t r0, r1, r2, r3;
                ldsm4(r0, r1, r2, r3, aB + off);
                bh[2 * bg][0] = r0; bh[2 * bg + 1][0] = r1;
                bh[2 * bg][1] = r2; bh[2 * bg + 1][1] = r3;
            }
#pragma unroll
            for (int mt = 0; mt < 4; mt++)
#pragma unroll
                for (int nt = 0; nt < 8; nt++)
                    mma_fp16(acc[mt][nt], ah[mt], bh[nt][0], bh[nt][1]);
        }
        __syncthreads();  // compute(c) done: stage stg reusable at c+1's issue
    }

    // epilogue: + bias, relu, fp16, scatter to g_H
#pragma unroll
    for (int mt = 0; mt < 4; mt++) {
        int r0i = wm + mt * 16 + (l >> 2);
        int ra = rows[r0i], rb = rows[r0i + 8];
#pragma unroll
        for (int nt = 0; nt < 8; nt++) {
            int cl = wn + nt * 8 + (l & 3) * 2;
            float b0 = bias[cl], b1v = bias[cl + 1];
            if (ra >= 0) {
                uint32_t h = packh2(fmaxf(acc[mt][nt][0] + b0, 0.f),
                                    fmaxf(acc[mt][nt][1] + b1v, 0.f));
                *(uint32_t*)(&g_H[(size_t)ra * FDIM2 + nbase + cl]) = h;
            }
            if (rb >= 0) {
                uint32_t h = packh2(fmaxf(acc[mt][nt][2] + b0, 0.f),
                                    fmaxf(acc[mt][nt][3] + b1v, 0.f));
                *(uint32_t*)(&g_H[(size_t)rb * FDIM2 + nbase + cl]) = h;
            }
        }
    }
#undef L1_ISSUE
}

// ---------------- layer 2: fp16 mma.sync, K-chunk 64, cp.async, softmax -----
// CTA: 128 rows x 64 cols, K=512 in 8 chunks of 64. 8 warps = 4(M) x 2(N).
#define L2_ROWS 0
#define L2_B2S 512
#define L2_BASE 1024
#define L2_ASTG 18432
#define L2_STG 27648
#define L2_SMEM (1024 + 2 * L2_STG)

__global__ __launch_bounds__(256) void k_gemm2(
    const float* __restrict__ b2, float* __restrict__ out)
{
    const int e = blockIdx.y;
    const int cnt = g_cnt[e];
    const int mbase = blockIdx.x * 128;
    if (mbase >= cnt) return;

    extern __shared__ __align__(16) char sm2[];
    int* rows = (int*)(sm2 + L2_ROWS);
    float* b2s = (float*)(sm2 + L2_B2S);
    const uint32_t sb = smem_u32(sm2);

    const int t = threadIdx.x;
    if (t < 128) {
        int p = mbase + t;
        rows[t] = (p < cnt) ? g_idx[e * BATCH + p] : -1;
    }
    if (t < 64) b2s[t] = b2[e * NCLS + t];
    __syncthreads();

    const int lr = t >> 1;
    const int seg = t & 1;
    const int hr = rows[lr];
    const __half* hp = (hr >= 0) ? g_H + (size_t)hr * FDIM2 + seg * 32 : g_H;
    const int hsz = (hr >= 0) ? 16 : 0;
    const uint32_t aOff = lr * (APITCH1 * 2) + seg * 64;
    const int br = t >> 2, bs = t & 3;
    const __half* wp = g_W2t + (size_t)(e * NCLS + br) * FDIM2 + bs * 16;
    const uint32_t bOff = br * (APITCH1 * 2) + bs * 32;

#define L2_ISSUE(kc, stg)                                                  \
    do {                                                                   \
        uint32_t ba = sb + L2_BASE + (stg) * L2_STG;                       \
        cpasync16z(ba + aOff,      hp + (kc), hsz);                        \
        cpasync16z(ba + aOff + 16, hp + (kc) + 8, hsz);                    \
        cpasync16z(ba + aOff + 32, hp + (kc) + 16, hsz);                   \
        cpasync16z(ba + aOff + 48, hp + (kc) + 24, hsz);                   \
        cpasync16(ba + L2_ASTG + bOff,      wp + (kc));                    \
        cpasync16(ba + L2_ASTG + bOff + 16, wp + (kc) + 8);                \
        CP_COMMIT();                                                       \
    } while (0)

    const int l = t & 31, wid = t >> 5;
    const int wm = (wid >> 1) * 32, wn = (wid & 1) * 32;
    const int lrow = l & 15;
    const int lk = (l >> 4) * 8;

    float acc[2][4][4];
#pragma unroll
    for (int i = 0; i < 2; i++)
#pragma unroll
        for (int j = 0; j < 4; j++)
#pragma unroll
            for (int q = 0; q < 4; q++) acc[i][j][q] = 0.f;

    L2_ISSUE(0, 0);

    for (int c = 0; c < 8; c++) {
        const int stg = c & 1;
        __syncthreads();
        if (c + 1 < 8) {
            L2_ISSUE((c + 1) * 64, stg ^ 1);
            CP_WAIT(1);
        } else {
            CP_WAIT(0);
        }
        __syncthreads();

        const uint32_t aA = sb + L2_BASE + stg * L2_STG;
        const uint32_t aB = aA + L2_ASTG;
#pragma unroll
        for (int ks = 0; ks < 64; ks += 16) {
            uint32_t ah[2][4], bh[4][2];
#pragma unroll
            for (int mt = 0; mt < 2; mt++) {
                uint32_t off = ((wm + mt * 16 + lrow) * APITCH1 + ks + lk) * 2;
                ldsm4(ah[mt][0], ah[mt][1], ah[mt][2], ah[mt][3], aA + off);
            }
#pragma unroll
            for (int bg = 0; bg < 2; bg++) {
                uint32_t off = ((wn + bg * 16 + lrow) * APITCH1 + ks + lk) * 2;
                uint32_t r0, r1, r2, r3;
                ldsm4(r0, r1, r2, r3, aB + off);
                bh[2 * bg][0] = r0; bh[2 * bg + 1][0] = r1;
                bh[2 * bg][1] = r2; bh[2 * bg + 1][1] = r3;
            }
#pragma unroll
            for (int mt = 0; mt < 2; mt++)
#pragma unroll
                for (int nt = 0; nt < 4; nt++)
                    mma_fp16(acc[mt][nt], ah[mt], bh[nt][0], bh[nt][1]);
        }
    }

    // logits -> smem (stage union), then per-thread softmax
    __syncthreads();
    float* lg = (float*)(sm2 + L2_BASE);  // [128][68]
#pragma unroll
    for (int mt = 0; mt < 2; mt++) {
        int r0i = wm + mt * 16 + (l >> 2);
#pragma unroll
        for (int nt = 0; nt < 4; nt++) {
            int cl = wn + nt * 8 + (l & 3) * 2;
            lg[r0i * 68 + cl]           = acc[mt][nt][0];
            lg[r0i * 68 + cl + 1]       = acc[mt][nt][1];
            lg[(r0i + 8) * 68 + cl]     = acc[mt][nt][2];
            lg[(r0i + 8) * 68 + cl + 1] = acc[mt][nt][3];
        }
    }
    __syncthreads();

    if (t < 128) {
        int r = rows[t];
        if (r >= 0) {
            float v[64];
            float mx = -3.4e38f;
#pragma unroll
            for (int j = 0; j < 64; j++) {
                v[j] = lg[t * 68 + j] + b2s[j];
                mx = fmaxf(mx, v[j]);
            }
            float s = 0.f;
#pragma unroll
            for (int j = 0; j < 64; j++) {
                v[j] = __expf(v[j] - mx);
                s += v[j];
            }
            float inv = 1.0f / s;
            float4* op = (float4*)(out + (size_t)r * NCLS);
#pragma unroll
            for (int q = 0; q < 16; q++)
                op[q] = make_float4(v[4 * q] * inv, v[4 * q + 1] * inv,
                                    v[4 * q + 2] * inv, v[4 * q + 3] * inv);
        }
    }
#undef L2_ISSUE
}

// ---------------------------------------------------------------------------
extern "C" void kernel_launch(void* const* d_in, const int* in_sizes, int n_in,
                              void* d_out, int out_size)
{
    const int*   domain = (const int*)  d_in[0];
    const float* x      = (const float*)d_in[1];
    const float* W1     = (const float*)d_in[2];
    const float* b1     = (const float*)d_in[3];
    const float* W2     = (const float*)d_in[4];
    const float* b2     = (const float*)d_in[5];
    float* out = (float*)d_out;

    cudaFuncSetAttribute(k_gemm1, cudaFuncAttributeMaxDynamicSharedMemorySize, L1_SMEM);
    cudaFuncSetAttribute(k_gemm2, cudaFuncAttributeMaxDynamicSharedMemorySize, L2_SMEM);

    k_convX<<<(BATCH * FDIM1 / 8) / 256, 256>>>(x);                    // + counter reset
    k_convW<<<dim3(32, 18, N_EXPERTS), dim3(32, 8)>>>(W1, W2, domain); // + bucket
    k_gemm1<<<dim3(BATCH / 128, FDIM2 / 128, N_EXPERTS), 128, L1_SMEM>>>(b1);
    k_gemm2<<<dim3(BATCH / 128, N_EXPERTS), 256, L2_SMEM>>>(b2, out);
}

// round 15
// speedup vs baseline: 1.3333x; 1.0468x over previous
#include <cuda_runtime.h>
#include <cuda_fp16.h>
#include <cstdint>

#define N_EXPERTS 8
#define FDIM1 1024
#define FDIM2 512
#define NCLS 64
#define BATCH 16384
#define APITCH1 72   // smem pitch for K-chunk 64 (64 + 8 pad), conflict-free ldmatrix

// ---------------- scratch (static device arrays; allocation-free) ----------
__device__ __align__(16) __half g_W1t[N_EXPERTS * FDIM2 * FDIM1];
__device__ __align__(16) __half g_W2t[N_EXPERTS * NCLS * FDIM2];
__device__ __align__(16) __half g_X16[(size_t)BATCH * FDIM1];
__device__ __align__(16) __half g_H[(size_t)BATCH * FDIM2];
__device__ int g_idx[N_EXPERTS * BATCH];
__device__ int g_cnt[N_EXPERTS];   // reset each launch in k_convX

// ---------------- helpers ---------------------------------------------------
__device__ __forceinline__ uint32_t smem_u32(const void* p) {
    uint32_t a;
    asm("{ .reg .u64 t; cvta.to.shared.u64 t, %1; cvt.u32.u64 %0, t; }"
        : "=r"(a) : "l"(p));
    return a;
}

__device__ __forceinline__ void ldsm4(uint32_t& r0, uint32_t& r1, uint32_t& r2,
                                      uint32_t& r3, uint32_t addr) {
    asm volatile("ldmatrix.sync.aligned.m8n8.x4.shared.b16 {%0,%1,%2,%3}, [%4];"
                 : "=r"(r0), "=r"(r1), "=r"(r2), "=r"(r3) : "r"(addr));
}

__device__ __forceinline__ void mma_fp16(float* c, const uint32_t* a,
                                         uint32_t b0, uint32_t b1) {
    asm volatile(
        "mma.sync.aligned.m16n8k16.row.col.f32.f16.f16.f32 "
        "{%0,%1,%2,%3}, {%4,%5,%6,%7}, {%8,%9}, {%0,%1,%2,%3};"
        : "+f"(c[0]), "+f"(c[1]), "+f"(c[2]), "+f"(c[3])
        : "r"(a[0]), "r"(a[1]), "r"(a[2]), "r"(a[3]), "r"(b0), "r"(b1));
}

__device__ __forceinline__ void cpasync16(uint32_t dst, const void* src) {
    asm volatile("cp.async.ca.shared.global [%0], [%1], 16;"
                 :: "r"(dst), "l"(src) : "memory");
}
__device__ __forceinline__ void cpasync16z(uint32_t dst, const void* src, int sz) {
    asm volatile("cp.async.ca.shared.global [%0], [%1], 16, %2;"
                 :: "r"(dst), "l"(src), "r"(sz) : "memory");
}
#define CP_COMMIT() asm volatile("cp.async.commit_group;" ::: "memory")
#define CP_WAIT(n) asm volatile("cp.async.wait_group %0;" ::"n"(n) : "memory")

__device__ __forceinline__ uint32_t packh2(float v0, float v1) {
    __half2 h = __floats2half2_rn(v0, v1);
    return *(uint32_t*)&h;
}

// ---------------- prep kernels ----------------------------------------------
// convX also resets g_cnt (completes before k_convW's bucket blocks run)
__global__ void k_convX(const float* __restrict__ src) {
    if (blockIdx.x == 0 && threadIdx.x < N_EXPERTS) g_cnt[threadIdx.x] = 0;
    size_t i = ((size_t)blockIdx.x * blockDim.x + threadIdx.x) * 8;
    float4 a = *(const float4*)(src + i);
    float4 b = *(const float4*)(src + i + 4);
    uint4 o = make_uint4(packh2(a.x, a.y), packh2(a.z, a.w),
                         packh2(b.x, b.y), packh2(b.z, b.w));
    *(uint4*)(&g_X16[i]) = o;
}

// Merged: W1 transpose-convert, W2 transpose-convert, AND expert bucketing
// (bucket runs in the otherwise-idle blocks y>=16 && x>=16).
__global__ void k_convW(const float* __restrict__ W1,
                        const float* __restrict__ W2,
                        const int* __restrict__ domain) {
    __shared__ float tile[32][33];
    int e = blockIdx.z;
    int tx = threadIdx.x, ty = threadIdx.y;
    if (blockIdx.y < 16) {
        int kb = blockIdx.x * 32, nb = blockIdx.y * 32;
        const float* s = W1 + ((size_t)e * FDIM1 + kb) * FDIM2 + nb;
#pragma unroll
        for (int i = 0; i < 32; i += 8) tile[ty + i][tx] = s[(size_t)(ty + i) * FDIM2 + tx];
        __syncthreads();
        size_t ob = ((size_t)e * FDIM2 + nb) * FDIM1 + kb;
#pragma unroll
        for (int i = 0; i < 32; i += 8)
            g_W1t[ob + (size_t)(ty + i) * FDIM1 + tx] = __float2half_rn(tile[tx][ty + i]);
    } else if (blockIdx.x < 16) {
        int kb = blockIdx.x * 32, nb = (blockIdx.y - 16) * 32;
        const float* s = W2 + ((size_t)e * FDIM2 + kb) * NCLS + nb;
#pragma unroll
        for (int i = 0; i < 32; i += 8) tile[ty + i][tx] = s[(size_t)(ty + i) * NCLS + tx];
        __syncthreads();
        size_t ob = ((size_t)e * NCLS + nb) * FDIM2 + kb;
#pragma unroll
        for (int i = 0; i < 32; i += 8)
            g_W2t[ob + (size_t)(ty + i) * FDIM2 + tx] = __float2half_rn(tile[tx][ty + i]);
    } else {
        // bucket: 256 spare blocks x 256 threads; need first 64 blocks
        int bi = (e * 2 + (blockIdx.y - 16)) * 16 + (blockIdx.x - 16);  // 0..255
        if (bi < 64) {
            int i = bi * 256 + ty * 32 + tx;
            int ex = domain[i];
            int p = atomicAdd(&g_cnt[ex], 1);
            g_idx[ex * BATCH + p] = i;
        }
    }
}

// ---------------- layer 1: fp16 mma.sync GEMM, warp tile 64x64 --------------
// CTA: 128 rows x 128 cols, K=1024 in 16 chunks of 64.
// 128 threads = 4 warps = 2(M) x 2(N), each warp computes 64x64.
// 2-stage double buffer; A (ZFILL gather) + B via cp.async + wait(1).
#define L1_ROWS 0
#define L1_BIAS 512
#define L1_BASE 1024
#define L1_ASTG 18432
#define L1_STG 36864
#define L1_SMEM (1024 + 2 * L1_STG)

__global__ __launch_bounds__(128, 2) void k_gemm1(const float* __restrict__ b1)
{
    const int e = blockIdx.z;
    const int cnt = g_cnt[e];
    const int mbase = blockIdx.x * 128;
    if (mbase >= cnt) return;
    const int nbase = blockIdx.y * 128;

    extern __shared__ __align__(16) char sm1[];
    int* rows = (int*)(sm1 + L1_ROWS);
    float* bias = (float*)(sm1 + L1_BIAS);
    const uint32_t sb = smem_u32(sm1);

    const int t = threadIdx.x;
    {
        int p = mbase + t;
        rows[t] = (p < cnt) ? g_idx[e * BATCH + p] : -1;
        bias[t] = b1[e * FDIM2 + nbase + t];
    }
    __syncthreads();

    // loader mappings: thread t -> rows lr0=t>>1, lr1=lr0+64; segment seg=t&1
    const int lr0 = t >> 1;
    const int lr1 = lr0 + 64;
    const int seg = t & 1;
    const int xr0 = rows[lr0], xr1 = rows[lr1];
    const __half* xp0 = (xr0 >= 0) ? g_X16 + (size_t)xr0 * FDIM1 + seg * 32 : g_X16;
    const __half* xp1 = (xr1 >= 0) ? g_X16 + (size_t)xr1 * FDIM1 + seg * 32 : g_X16;
    const int xsz0 = (xr0 >= 0) ? 16 : 0;
    const int xsz1 = (xr1 >= 0) ? 16 : 0;
    const __half* wp0 = g_W1t + (size_t)(e * FDIM2 + nbase + lr0) * FDIM1 + seg * 32;
    const __half* wp1 = g_W1t + (size_t)(e * FDIM2 + nbase + lr1) * FDIM1 + seg * 32;
    const uint32_t tOff0 = lr0 * (APITCH1 * 2) + seg * 64;
    const uint32_t tOff1 = lr1 * (APITCH1 * 2) + seg * 64;

#define L1_ISSUE(kc, stg)                                                  \
    do {                                                                   \
        uint32_t ba = sb + L1_BASE + (stg) * L1_STG;                       \
        cpasync16z(ba + tOff0,      xp0 + (kc), xsz0);                     \
        cpasync16z(ba + tOff0 + 16, xp0 + (kc) + 8, xsz0);                 \
        cpasync16z(ba + tOff0 + 32, xp0 + (kc) + 16, xsz0);                \
        cpasync16z(ba + tOff0 + 48, xp0 + (kc) + 24, xsz0);                \
        cpasync16z(ba + tOff1,      xp1 + (kc), xsz1);                     \
        cpasync16z(ba + tOff1 + 16, xp1 + (kc) + 8, xsz1);                 \
        cpasync16z(ba + tOff1 + 32, xp1 + (kc) + 16, xsz1);                \
        cpasync16z(ba + tOff1 + 48, xp1 + (kc) + 24, xsz1);                \
        uint32_t bb = ba + L1_ASTG;                                        \
        cpasync16(bb + tOff0,      wp0 + (kc));                            \
        cpasync16(bb + tOff0 + 16, wp0 + (kc) + 8);                        \
        cpasync16(bb + tOff0 + 32, wp0 + (kc) + 16);                       \
        cpasync16(bb + tOff0 + 48, wp0 + (kc) + 24);                       \
        cpasync16(bb + tOff1,      wp1 + (kc));                            \
        cpasync16(bb + tOff1 + 16, wp1 + (kc) + 8);                        \
        cpasync16(bb + tOff1 + 32, wp1 + (kc) + 16);                       \
        cpasync16(bb + tOff1 + 48, wp1 + (kc) + 24);                       \
        CP_COMMIT();                                                       \
    } while (0)

    const int l = t & 31, wid = t >> 5;          // 4 warps
    const int wm = (wid >> 1) * 64, wn = (wid & 1) * 64;
    const int lrow = l & 15;
    const int lk = (l >> 4) * 8;

    float acc[4][8][4];
#pragma unroll
    for (int i = 0; i < 4; i++)
#pragma unroll
        for (int j = 0; j < 8; j++)
#pragma unroll
            for (int q = 0; q < 4; q++) acc[i][j][q] = 0.f;

    L1_ISSUE(0, 0);

    for (int c = 0; c < 16; c++) {
        const int stg = c & 1;
        if (c + 1 < 16) {
            L1_ISSUE((c + 1) * 64, stg ^ 1);  // next chunk into other stage
            CP_WAIT(1);                       // chunk c landed
        } else {
            CP_WAIT(0);
        }
        __syncthreads();

        const uint32_t aA = sb + L1_BASE + stg * L1_STG;
        const uint32_t aB = aA + L1_ASTG;
#pragma unroll
        for (int ks = 0; ks < 64; ks += 16) {
            uint32_t ah[4][4], bh[8][2];
#pragma unroll
            for (int mt = 0; mt < 4; mt++) {
                uint32_t off = ((wm + mt * 16 + lrow) * APITCH1 + ks + lk) * 2;
                ldsm4(ah[mt][0], ah[mt][1], ah[mt][2], ah[mt][3], aA + off);
            }
#pragma unroll
            for (int bg = 0; bg < 4; bg++) {
                uint32_t off = ((wn + bg * 16 + lrow) * APITCH1 + ks + lk) * 2;
                uint32_t r0, r1, r2, r3;
                ldsm4(r0, r1, r2, r3, aB + off);
                bh[2 * bg][0] = r0; bh[2 * bg + 1][0] = r1;
                bh[2 * bg][1] = r2; bh[2 * bg + 1][1] = r3;
            }
#pragma unroll
            for (int mt = 0; mt < 4; mt++)
#pragma unroll
                for (int nt = 0; nt < 8; nt++)
                    mma_fp16(acc[mt][nt], ah[mt], bh[nt][0], bh[nt][1]);
        }
        __syncthreads();  // compute(c) done: stage stg reusable at c+1's issue
    }

    // epilogue: + bias, relu, fp16, scatter to g_H
#pragma unroll
    for (int mt = 0; mt < 4; mt++) {
        int r0i = wm + mt * 16 + (l >> 2);
        int ra = rows[r0i], rb = rows[r0i + 8];
#pragma unroll
        for (int nt = 0; nt < 8; nt++) {
            int cl = wn + nt * 8 + (l & 3) * 2;
            float b0 = bias[cl], b1v = bias[cl + 1];
            if (ra >= 0) {
                uint32_t h = packh2(fmaxf(acc[mt][nt][0] + b0, 0.f),
                                    fmaxf(acc[mt][nt][1] + b1v, 0.f));
                *(uint32_t*)(&g_H[(size_t)ra * FDIM2 + nbase + cl]) = h;
            }
            if (rb >= 0) {
                uint32_t h = packh2(fmaxf(acc[mt][nt][2] + b0, 0.f),
                                    fmaxf(acc[mt][nt][3] + b1v, 0.f));
                *(uint32_t*)(&g_H[(size_t)rb * FDIM2 + nbase + cl]) = h;
            }
        }
    }
#undef L1_ISSUE
}

// ---------------- layer 2: fp16 mma.sync, m-tile 64, K-chunk 64, softmax ----
// CTA: 64 rows x 64 cols, K=512 in 8 chunks of 64. 8 warps = 4(M=16) x 2(N=32).
// ~256 working CTAs (vs 128 at m=128) -> ~2 CTAs/SM for latency overlap.
#define L2_ROWS 0
#define L2_B2S 256
#define L2_BASE 1024
#define L2_ASTG 9216
#define L2_STG 18432
#define L2_SMEM (1024 + 2 * L2_STG)

__global__ __launch_bounds__(256) void k_gemm2(
    const float* __restrict__ b2, float* __restrict__ out)
{
    const int e = blockIdx.y;
    const int cnt = g_cnt[e];
    const int mbase = blockIdx.x * 64;
    if (mbase >= cnt) return;

    extern __shared__ __align__(16) char sm2[];
    int* rows = (int*)(sm2 + L2_ROWS);
    float* b2s = (float*)(sm2 + L2_B2S);
    const uint32_t sb = smem_u32(sm2);

    const int t = threadIdx.x;
    if (t < 64) {
        int p = mbase + t;
        rows[t] = (p < cnt) ? g_idx[e * BATCH + p] : -1;
        b2s[t] = b2[e * NCLS + t];
    }
    __syncthreads();

    // loaders: row lr = t>>2 (0..63), segment seg = t&3 (16 halfs = 32 B each)
    const int lr = t >> 2;
    const int seg = t & 3;
    const int hr = rows[lr];
    const __half* hp = (hr >= 0) ? g_H + (size_t)hr * FDIM2 + seg * 16 : g_H;
    const int hsz = (hr >= 0) ? 16 : 0;
    const __half* wp = g_W2t + (size_t)(e * NCLS + lr) * FDIM2 + seg * 16;
    const uint32_t tOff = lr * (APITCH1 * 2) + seg * 32;

#define L2_ISSUE(kc, stg)                                                  \
    do {                                                                   \
        uint32_t ba = sb + L2_BASE + (stg) * L2_STG;                       \
        cpasync16z(ba + tOff,      hp + (kc), hsz);                        \
        cpasync16z(ba + tOff + 16, hp + (kc) + 8, hsz);                    \
        uint32_t bb = ba + L2_ASTG;                                        \
        cpasync16(bb + tOff,      wp + (kc));                              \
        cpasync16(bb + tOff + 16, wp + (kc) + 8);                          \
        CP_COMMIT();                                                       \
    } while (0)

    const int l = t & 31, wid = t >> 5;
    const int wm = (wid >> 1) * 16, wn = (wid & 1) * 32;
    const int lrow = l & 15;
    const int lk = (l >> 4) * 8;

    float acc[4][4];
#pragma unroll
    for (int j = 0; j < 4; j++)
#pragma unroll
        for (int q = 0; q < 4; q++) acc[j][q] = 0.f;

    L2_ISSUE(0, 0);

    for (int c = 0; c < 8; c++) {
        const int stg = c & 1;
        if (c + 1 < 8) {
            L2_ISSUE((c + 1) * 64, stg ^ 1);
            CP_WAIT(1);
        } else {
            CP_WAIT(0);
        }
        __syncthreads();

        const uint32_t aA = sb + L2_BASE + stg * L2_STG;
        const uint32_t aB = aA + L2_ASTG;
#pragma unroll
        for (int ks = 0; ks < 64; ks += 16) {
            uint32_t ah[4];
            {
                uint32_t off = ((wm + lrow) * APITCH1 + ks + lk) * 2;
                ldsm4(ah[0], ah[1], ah[2], ah[3], aA + off);
            }
#pragma unroll
            for (int bg = 0; bg < 2; bg++) {
                uint32_t off = ((wn + bg * 16 + lrow) * APITCH1 + ks + lk) * 2;
                uint32_t r0, r1, r2, r3;
                ldsm4(r0, r1, r2, r3, aB + off);
                mma_fp16(acc[2 * bg],     ah, r0, r2);
                mma_fp16(acc[2 * bg + 1], ah, r1, r3);
            }
        }
        __syncthreads();
    }

    // logits -> smem (stage union), then per-thread softmax over 64 rows
    float* lg = (float*)(sm2 + L2_BASE);  // [64][68]
    {
        int r0i = wm + (l >> 2);
#pragma unroll
        for (int nt = 0; nt < 4; nt++) {
            int cl = wn + nt * 8 + (l & 3) * 2;
            lg[r0i * 68 + cl]           = acc[nt][0];
            lg[r0i * 68 + cl + 1]       = acc[nt][1];
            lg[(r0i + 8) * 68 + cl]     = acc[nt][2];
            lg[(r0i + 8) * 68 + cl + 1] = acc[nt][3];
        }
    }
    __syncthreads();

    if (t < 64) {
        int r = rows[t];
        if (r >= 0) {
            float v[64];
            float mx = -3.4e38f;
#pragma unroll
            for (int j = 0; j < 64; j++) {
                v[j] = lg[t * 68 + j] + b2s[j];
                mx = fmaxf(mx, v[j]);
            }
            float s = 0.f;
#pragma unroll
            for (int j = 0; j < 64; j++) {
                v[j] = __expf(v[j] - mx);
                s += v[j];
            }
            float inv = 1.0f / s;
            float4* op = (float4*)(out + (size_t)r * NCLS);
#pragma unroll
            for (int q = 0; q < 16; q++)
                op[q] = make_float4(v[4 * q] * inv, v[4 * q + 1] * inv,
                                    v[4 * q + 2] * inv, v[4 * q + 3] * inv);
        }
    }
#undef L2_ISSUE
}

// ---------------------------------------------------------------------------
extern "C" void kernel_launch(void* const* d_in, const int* in_sizes, int n_in,
                              void* d_out, int out_size)
{
    const int*   domain = (const int*)  d_in[0];
    const float* x      = (const float*)d_in[1];
    const float* W1     = (const float*)d_in[2];
    const float* b1     = (const float*)d_in[3];
    const float* W2     = (const float*)d_in[4];
    const float* b2     = (const float*)d_in[5];
    float* out = (float*)d_out;

    cudaFuncSetAttribute(k_gemm1, cudaFuncAttributeMaxDynamicSharedMemorySize, L1_SMEM);
    cudaFuncSetAttribute(k_gemm2, cudaFuncAttributeMaxDynamicSharedMemorySize, L2_SMEM);

    k_convX<<<(BATCH * FDIM1 / 8) / 256, 256>>>(x);                    // + counter reset
    k_convW<<<dim3(32, 18, N_EXPERTS), dim3(32, 8)>>>(W1, W2, domain); // + bucket
    k_gemm1<<<dim3(BATCH / 128, FDIM2 / 128, N_EXPERTS), 128, L1_SMEM>>>(b1);
    k_gemm2<<<dim3(BATCH / 64, N_EXPERTS), 256, L2_SMEM>>>(b2, out);
}